// round 12
// baseline (speedup 1.0000x reference)
#include <cuda_runtime.h>
#include <cuda_bf16.h>
#include <stdint.h>

// ---------------- problem constants ----------------
#define N_GRAPHS        64
#define NODES_PER_GRAPH 1024
#define N_NODES         (N_GRAPHS * NODES_PER_GRAPH)   // 65536
#define N_EDGES         (N_NODES * 32)                 // 2097152
#define EPG             (N_EDGES / N_GRAPHS)           // 32768 edges per graph
#define D_FEAT          256
#define D_VEC4          (D_FEAT / 4)                   // 64
#define KSEL            512                            // kept nodes per graph
#define N_KEPT          (N_GRAPHS * KSEL)              // 32768
#define BKT_CAP         96                             // max in-degree (Binom mean 32, sd 5.6)

#define SEG_WARPS       8                              // warps per k_scatter block
#define SEG_EDGES       (EPG / SEG_WARPS)              // 4096 edges per warp segment
#define SEG_ITERS       (SEG_EDGES / 32)               // 128

// output layout (flattened, float32): x_new | new_edge_index | batch_new
#define OUT_E  (N_KEPT * D_FEAT)                       // 8388608
#define OUT_B  (OUT_E + 2 * N_EDGES)                   // 12582912

// fused epilogue grid split
#define GATHER_BLOCKS  ((N_KEPT * D_VEC4) / 256)       // 8192
#define EDGE_BLOCKS    ((N_EDGES / 4) / 256)           // 2048
#define EPI_BLOCKS     (GATHER_BLOCKS + EDGE_BLOCKS)   // 10240

// ---------------- device scratch (no allocation allowed) ----------------
__device__ float g_xw1[N_NODES];
__device__ float g_xwg[N_NODES];
__device__ int   g_degi[N_NODES];
__device__ float g_gcn[N_NODES];
__device__ float g_bktf[(size_t)N_NODES * BKT_CAP];    // terms in edge-id order per node
__device__ int   g_perm[N_KEPT];
__device__ float g_mult[N_KEPT];
__device__ int   g_nodemap[N_NODES];

// ---------------- kernels ----------------

// One THREAD per node row; strict sequential FMA chain over k ascending —
// replicates XLA:CPU gemv per-output accumulation order.
__global__ __launch_bounds__(128) void k_dot(const float4* __restrict__ x4,
                                             const float* __restrict__ w1,
                                             const float* __restrict__ wg) {
    __shared__ float s_w1[D_FEAT];
    __shared__ float s_wg[D_FEAT];
    int tid = threadIdx.x;
    for (int i = tid; i < D_FEAT; i += 128) {
        s_w1[i] = w1[i];
        s_wg[i] = wg[i];
    }
    __syncthreads();
    int row = blockIdx.x * 128 + tid;
    const float4* xr = x4 + (size_t)row * D_VEC4;
    float s1 = 0.f, s2 = 0.f;
#pragma unroll 8
    for (int q = 0; q < D_VEC4; q++) {
        float4 xv = xr[q];
        int k = q * 4;
        s1 = __fmaf_rn(xv.x, s_w1[k + 0], s1);
        s1 = __fmaf_rn(xv.y, s_w1[k + 1], s1);
        s1 = __fmaf_rn(xv.z, s_w1[k + 2], s1);
        s1 = __fmaf_rn(xv.w, s_w1[k + 3], s1);
        s2 = __fmaf_rn(xv.x, s_wg[k + 0], s2);
        s2 = __fmaf_rn(xv.y, s_wg[k + 1], s2);
        s2 = __fmaf_rn(xv.z, s_wg[k + 2], s2);
        s2 = __fmaf_rn(xv.w, s_wg[k + 3], s2);
    }
    g_xw1[row] = s1;
    g_xwg[row] = s2;
}

// One block per graph: deterministic ORDERED scatter of GCN terms.
// Phase 1: per-warp-segment degree histograms (smem int atomics — exact).
// Phase 2: per-dst exclusive prefix across segments; deg -> g_degi + dis (smem).
// Phase 3: each warp re-walks its segment in edge order; slot = seg_base[c] +
//          intra-warp rank (match_any+popc). Terms land in g_bktf already in
//          ascending-edge-id order -> no sort needed downstream.
// term = fl(fl(dis_r*dis_c) * xwg_r) — exactly the reference expression tree.
__global__ __launch_bounds__(256) void k_scatter(const int* __restrict__ row,
                                                 const int* __restrict__ col) {
    __shared__ int   hist[SEG_WARPS][NODES_PER_GRAPH];   // 32 KB
    __shared__ float disl[NODES_PER_GRAPH];              // 4 KB
    __shared__ float xwgl[NODES_PER_GRAPH];              // 4 KB
    int g    = blockIdx.x;
    int tid  = threadIdx.x;
    int w    = tid >> 5;
    int lane = tid & 31;

    for (int i = tid; i < NODES_PER_GRAPH; i += 256) {
        xwgl[i] = g_xwg[g * NODES_PER_GRAPH + i];
#pragma unroll
        for (int ww = 0; ww < SEG_WARPS; ww++) hist[ww][i] = 0;
    }
    __syncthreads();

    int ebase = g * EPG + w * SEG_EDGES;

    // phase 1: per-warp histogram of its segment
#pragma unroll 2
    for (int it = 0; it < SEG_ITERS; it++) {
        int e = ebase + it * 32 + lane;
        int r = row[e], c = col[e];
        if (r != c) atomicAdd(&hist[w][c & (NODES_PER_GRAPH - 1)], 1);
    }
    __syncthreads();

    // phase 2: exclusive prefix over segments per dst; deg; dis
    for (int c = tid; c < NODES_PER_GRAPH; c += 256) {
        int run = 0;
#pragma unroll
        for (int ww = 0; ww < SEG_WARPS; ww++) {
            int t = hist[ww][c];
            hist[ww][c] = run;
            run += t;
        }
        g_degi[g * NODES_PER_GRAPH + c] = run;
        // 1.0f/sqrtf, both correctly rounded (matches XLA CPU rsqrt)
        disl[c] = (run > 0) ? __fdiv_rn(1.0f, __fsqrt_rn((float)run)) : 0.0f;
    }
    __syncthreads();

    // phase 3: ordered scatter (warp walks its segment in ascending edge id)
    for (int it = 0; it < SEG_ITERS; it++) {
        int e  = ebase + it * 32 + lane;
        int rv = row[e], cv = col[e];
        int r  = rv & (NODES_PER_GRAPH - 1);
        int c  = cv & (NODES_PER_GRAPH - 1);
        bool valid = (rv != cv);
        unsigned mm  = __match_any_sync(0xFFFFFFFFu, c);
        unsigned vm  = __ballot_sync(0xFFFFFFFFu, valid);
        unsigned grp = mm & vm;
        int base = 0;
        if (valid) base = hist[w][c];          // converged read (broadcast per group)
        __syncwarp();                           // reads complete before cursor update
        if (valid) {
            int rank = __popc(grp & ((1u << lane) - 1));
            int slot = base + rank;
            if (slot < BKT_CAP) {
                float term = __fmul_rn(__fmul_rn(disl[r], disl[c]), xwgl[r]);
                g_bktf[(size_t)(g * NODES_PER_GRAPH + c) * BKT_CAP + slot] = term;
            }
            if (lane == __ffs(grp) - 1)         // group leader advances cursor
                hist[w][c] = base + __popc(grp);
        }
        __syncwarp();                           // cursor visible to next iteration
    }
}

// One WARP per destination node: terms are already in ascending-edge-id order;
// sequential fp32 left-fold via register shuffles (bit-replicates XLA:CPU's
// serial scatter-add). Predicated adds — no spurious +0.0 terms.
__global__ __launch_bounds__(256) void k_fold() {
    int w    = threadIdx.x >> 5;
    int lane = threadIdx.x & 31;
    int c    = blockIdx.x * 8 + w;
    int n    = g_degi[c];
    if (n > BKT_CAP) n = BKT_CAP;
    const float* b = &g_bktf[(size_t)c * BKT_CAP];
    float v0 = (lane < n)      ? b[lane]      : 0.0f;
    float v1 = (32 + lane < n) ? b[32 + lane] : 0.0f;
    float s = 0.0f;
#pragma unroll
    for (int j = 0; j < 32; j++) {
        float u = __shfl_sync(0xFFFFFFFFu, v0, j);
        if (j < n) s = __fadd_rn(s, u);
    }
#pragma unroll
    for (int j = 0; j < 32; j++) {
        float u = __shfl_sync(0xFFFFFFFFu, v1, j);
        if (32 + j < n) s = __fadd_rn(s, u);
    }
    for (int i = 64; i < n; i++)               // rare tail (deg > 64)
        s = __fadd_rn(s, b[i]);
    if (lane == 0) g_gcn[c] = s;
}

// per-graph full bitonic sort of 1024 (score, idx) keys.
// key = (~ordered(score) << 32) | idx -> ascending sort == descending score,
// ties broken by lower original index (matches jax.lax.top_k).
// Also writes batch_new (fused).
__global__ __launch_bounds__(512) void k_sort(const float* __restrict__ b1,
                                              const float* __restrict__ bg,
                                              float* __restrict__ out) {
    __shared__ unsigned long long keys[NODES_PER_GRAPH];
    __shared__ float sc[NODES_PER_GRAPH];
    int g = blockIdx.x;
    float b1v = b1[0], bgv = bg[0];

    for (int i = threadIdx.x; i < NODES_PER_GRAPH; i += 512) {
        int n = g * NODES_PER_GRAPH + i;
        // 0.5* mults exact (pow2); single rounding in final add, like ref
        float s = __fadd_rn(__fmul_rn(0.5f, __fadd_rn(g_xw1[n], b1v)),
                            __fmul_rn(0.5f, __fadd_rn(g_gcn[n], bgv)));
        sc[i] = s;
        unsigned u = __float_as_uint(s);
        u ^= (u & 0x80000000u) ? 0xFFFFFFFFu : 0x80000000u;  // monotonic asc map
        u = ~u;                                              // descending score
        keys[i] = ((unsigned long long)u << 32) | (unsigned)i;
    }
    __syncthreads();

    for (int k = 2; k <= NODES_PER_GRAPH; k <<= 1) {
        for (int j = k >> 1; j > 0; j >>= 1) {
            int t = threadIdx.x;
            int i = 2 * t - (t & (j - 1));   // index with bit j clear
            int ixj = i | j;
            unsigned long long a = keys[i], bb = keys[ixj];
            bool asc = ((i & k) == 0);
            if ((a > bb) == asc) { keys[i] = bb; keys[ixj] = a; }
            __syncthreads();
        }
    }

    for (int j = threadIdx.x; j < NODES_PER_GRAPH; j += 512) {
        int li = (int)(keys[j] & 0xFFFFFFFFull);
        int n  = g * NODES_PER_GRAPH + li;
        if (j < KSEL) {
            int pos = g * KSEL + j;
            g_perm[pos]      = n;
            g_mult[pos]      = tanhf(sc[li]);
            g_nodemap[n]     = pos;
            out[OUT_B + pos] = (float)g;   // fused batch_new
        } else {
            g_nodemap[n]     = -1;
        }
    }
}

// Fused epilogue: blocks [0, GATHER_BLOCKS) gather x_new; the rest relabel edges.
__global__ void k_epilogue(const float4* __restrict__ x4,
                           const int4* __restrict__ ei4,
                           float* __restrict__ out) {
    int b = blockIdx.x;
    if (b < GATHER_BLOCKS) {
        // x_new[i] = x[perm[i]] * tanh(score[perm[i]])   (float4 lanes)
        int tid = b * 256 + threadIdx.x;
        int i = tid >> 6;         // kept-row index
        int q = tid & 63;         // float4 lane within row
        float m = g_mult[i];
        float4 v = x4[(size_t)g_perm[i] * D_VEC4 + q];
        v.x = __fmul_rn(v.x, m); v.y = __fmul_rn(v.y, m);
        v.z = __fmul_rn(v.z, m); v.w = __fmul_rn(v.w, m);
        ((float4*)out)[tid] = v;
    } else {
        // relabel edges, 4 edges/thread; invalid edges -> (-1,-1)
        int t = (b - GATHER_BLOCKS) * 256 + threadIdx.x;
        if (t >= N_EDGES / 4) return;
        int4 r = ei4[t];
        int4 c = ei4[N_EDGES / 4 + t];
        int er0 = g_nodemap[r.x], ec0 = g_nodemap[c.x];
        int er1 = g_nodemap[r.y], ec1 = g_nodemap[c.y];
        int er2 = g_nodemap[r.z], ec2 = g_nodemap[c.z];
        int er3 = g_nodemap[r.w], ec3 = g_nodemap[c.w];
        float4 ro, co;
        ro.x = (er0 >= 0 && ec0 >= 0) ? (float)er0 : -1.0f;
        co.x = (er0 >= 0 && ec0 >= 0) ? (float)ec0 : -1.0f;
        ro.y = (er1 >= 0 && ec1 >= 0) ? (float)er1 : -1.0f;
        co.y = (er1 >= 0 && ec1 >= 0) ? (float)ec1 : -1.0f;
        ro.z = (er2 >= 0 && ec2 >= 0) ? (float)er2 : -1.0f;
        co.z = (er2 >= 0 && ec2 >= 0) ? (float)ec2 : -1.0f;
        ro.w = (er3 >= 0 && ec3 >= 0) ? (float)er3 : -1.0f;
        co.w = (er3 >= 0 && ec3 >= 0) ? (float)ec3 : -1.0f;
        ((float4*)(out + OUT_E))[t]           = ro;
        ((float4*)(out + OUT_E + N_EDGES))[t] = co;
    }
}

// ---------------- launch ----------------
extern "C" void kernel_launch(void* const* d_in, const int* in_sizes, int n_in,
                              void* d_out, int out_size) {
    const float* x   = (const float*)d_in[0];
    const int*   ei  = (const int*)  d_in[1];
    // d_in[2] = batch (unused: analytic)
    const float* w1  = (const float*)d_in[3];
    const float* b1  = (const float*)d_in[4];
    const float* wg  = (const float*)d_in[5];
    const float* bg  = (const float*)d_in[6];
    float* out = (float*)d_out;

    k_dot<<<N_NODES / 128, 128>>>((const float4*)x, w1, wg);
    k_scatter<<<N_GRAPHS, 256>>>(ei, ei + N_EDGES);
    k_fold<<<N_NODES / 8, 256>>>();
    k_sort<<<N_GRAPHS, 512>>>(b1, bg, out);
    k_epilogue<<<EPI_BLOCKS, 256>>>((const float4*)x, (const int4*)ei, out);
}

// round 13
// speedup vs baseline: 1.0843x; 1.0843x over previous
#include <cuda_runtime.h>
#include <cuda_bf16.h>
#include <stdint.h>

// ---------------- problem constants ----------------
#define N_GRAPHS        64
#define NODES_PER_GRAPH 1024
#define N_NODES         (N_GRAPHS * NODES_PER_GRAPH)   // 65536
#define N_EDGES         (N_NODES * 32)                 // 2097152
#define EPG             (N_EDGES / N_GRAPHS)           // 32768 edges per graph
#define D_FEAT          256
#define D_VEC4          (D_FEAT / 4)                   // 64
#define KSEL            512                            // kept nodes per graph
#define N_KEPT          (N_GRAPHS * KSEL)              // 32768
#define BKT_CAP         96                             // max in-degree (Binom mean 32, sd 5.6)

// k_scatter4 geometry: 4 destination-quarters per graph, 16 warps per block
#define NQ              4
#define C_PER_Q         (NODES_PER_GRAPH / NQ)         // 256
#define SC_WARPS        16
#define CHUNK_EDGES     (EPG / SC_WARPS)               // 2048
#define CH_ITERS        (CHUNK_EDGES / 32)             // 64

// output layout (flattened, float32): x_new | new_edge_index | batch_new
#define OUT_E  (N_KEPT * D_FEAT)                       // 8388608
#define OUT_B  (OUT_E + 2 * N_EDGES)                   // 12582912

// fused epilogue grid split
#define GATHER_BLOCKS  ((N_KEPT * D_VEC4) / 256)       // 8192
#define EDGE_BLOCKS    ((N_EDGES / 4) / 256)           // 2048
#define EPI_BLOCKS     (GATHER_BLOCKS + EDGE_BLOCKS)   // 10240

// ---------------- device scratch (no allocation allowed) ----------------
__device__ float g_xw1[N_NODES];
__device__ float g_xwg[N_NODES];
__device__ float g_dis[N_NODES];
__device__ int   g_degi[N_NODES];
__device__ float g_gcn[N_NODES];
__device__ float g_bktf[(size_t)N_NODES * BKT_CAP];    // terms in edge-id order per node
__device__ int   g_perm[N_KEPT];
__device__ float g_mult[N_KEPT];
__device__ int   g_nodemap[N_NODES];

// ---------------- kernels ----------------

// One THREAD per node row; strict sequential FMA chain over k ascending —
// replicates XLA:CPU gemv per-output accumulation order.
__global__ __launch_bounds__(128) void k_dot(const float4* __restrict__ x4,
                                             const float* __restrict__ w1,
                                             const float* __restrict__ wg) {
    __shared__ float s_w1[D_FEAT];
    __shared__ float s_wg[D_FEAT];
    int tid = threadIdx.x;
    for (int i = tid; i < D_FEAT; i += 128) {
        s_w1[i] = w1[i];
        s_wg[i] = wg[i];
    }
    __syncthreads();
    int row = blockIdx.x * 128 + tid;
    const float4* xr = x4 + (size_t)row * D_VEC4;
    float s1 = 0.f, s2 = 0.f;
#pragma unroll 8
    for (int q = 0; q < D_VEC4; q++) {
        float4 xv = xr[q];
        int k = q * 4;
        s1 = __fmaf_rn(xv.x, s_w1[k + 0], s1);
        s1 = __fmaf_rn(xv.y, s_w1[k + 1], s1);
        s1 = __fmaf_rn(xv.z, s_w1[k + 2], s1);
        s1 = __fmaf_rn(xv.w, s_w1[k + 3], s1);
        s2 = __fmaf_rn(xv.x, s_wg[k + 0], s2);
        s2 = __fmaf_rn(xv.y, s_wg[k + 1], s2);
        s2 = __fmaf_rn(xv.z, s_wg[k + 2], s2);
        s2 = __fmaf_rn(xv.w, s_wg[k + 3], s2);
    }
    g_xw1[row] = s1;
    g_xwg[row] = s2;
}

// One block per graph: smem degree histogram, fused dis = 1/sqrt(deg).
// (R8-proven kernel; integer smem atomics — order-independent, exact.)
__global__ __launch_bounds__(512) void k_degdis(const int4* __restrict__ ei4) {
    __shared__ int h[NODES_PER_GRAPH];
    int g = blockIdx.x;
    int tid = threadIdx.x;
    for (int i = tid; i < NODES_PER_GRAPH; i += 512) h[i] = 0;
    __syncthreads();
    int base4 = g * (EPG / 4);
    for (int t = tid; t < EPG / 4; t += 512) {
        int4 r = ei4[base4 + t];
        int4 c = ei4[N_EDGES / 4 + base4 + t];
        if (r.x != c.x) atomicAdd(&h[c.x & (NODES_PER_GRAPH - 1)], 1);
        if (r.y != c.y) atomicAdd(&h[c.y & (NODES_PER_GRAPH - 1)], 1);
        if (r.z != c.z) atomicAdd(&h[c.z & (NODES_PER_GRAPH - 1)], 1);
        if (r.w != c.w) atomicAdd(&h[c.w & (NODES_PER_GRAPH - 1)], 1);
    }
    __syncthreads();
    for (int i = tid; i < NODES_PER_GRAPH; i += 512) {
        int d = h[i];
        // 1.0f/sqrtf, both correctly rounded (matches XLA CPU rsqrt)
        g_dis[g * NODES_PER_GRAPH + i] =
            (d > 0) ? __fdiv_rn(1.0f, __fsqrt_rn((float)d)) : 0.0f;
    }
}

// 4 blocks per graph (one per destination-QUARTER): deterministic ORDERED
// scatter. Each block re-reads the graph's full edge slice but only handles
// edges whose dst falls in its quarter — block-private cursors, no global
// prefix, 256 blocks x 16 warps for SM coverage (fixes R11's 64-block stall).
// Phase 1: per-warp-chunk histogram of own-quarter dsts (smem atomics).
// Phase 2: exclusive prefix over the 16 chunks per dst; writes g_degi.
// Phase 3: warp walks its chunk in edge order; slot = chunk_base[c] +
//          intra-warp rank (match_any+popc). Terms land in g_bktf in
//          ascending-edge-id order.
// term = fl(fl(dis_r*dis_c) * xwg_r) — exactly the reference expression tree.
__global__ __launch_bounds__(512) void k_scatter4(const int* __restrict__ row,
                                                  const int* __restrict__ col) {
    __shared__ int   hist[SC_WARPS][C_PER_Q];            // 16 KB
    __shared__ float disl[NODES_PER_GRAPH];              // 4 KB
    __shared__ float xwgl[NODES_PER_GRAPH];              // 4 KB
    int g    = blockIdx.x >> 2;
    int h    = blockIdx.x & 3;                           // quarter
    int tid  = threadIdx.x;
    int w    = tid >> 5;
    int lane = tid & 31;

    for (int i = tid; i < NODES_PER_GRAPH; i += 512) {
        disl[i] = g_dis[g * NODES_PER_GRAPH + i];
        xwgl[i] = g_xwg[g * NODES_PER_GRAPH + i];
    }
    for (int i = tid; i < SC_WARPS * C_PER_Q; i += 512)
        ((int*)hist)[i] = 0;
    __syncthreads();

    int ebase = g * EPG + w * CHUNK_EDGES;

    // phase 1: per-warp-chunk histogram of own-quarter dsts
#pragma unroll 2
    for (int it = 0; it < CH_ITERS; it++) {
        int e = ebase + it * 32 + lane;
        int rv = row[e], cv = col[e];
        int cl = cv & (NODES_PER_GRAPH - 1);
        if (rv != cv && (cl >> 8) == h)
            atomicAdd(&hist[w][cl & (C_PER_Q - 1)], 1);
    }
    __syncthreads();

    // phase 2: exclusive prefix over chunks per dst; write g_degi
    if (tid < C_PER_Q) {
        int run = 0;
#pragma unroll
        for (int ww = 0; ww < SC_WARPS; ww++) {
            int t = hist[ww][tid];
            hist[ww][tid] = run;
            run += t;
        }
        g_degi[g * NODES_PER_GRAPH + h * C_PER_Q + tid] = run;
    }
    __syncthreads();

    // phase 3: ordered scatter (warp walks its chunk in ascending edge id)
    for (int it = 0; it < CH_ITERS; it++) {
        int e  = ebase + it * 32 + lane;
        int rv = row[e], cv = col[e];
        int rl = rv & (NODES_PER_GRAPH - 1);
        int cl = cv & (NODES_PER_GRAPH - 1);
        int cq = cl & (C_PER_Q - 1);
        bool valid = (rv != cv) && ((cl >> 8) == h);
        unsigned mm  = __match_any_sync(0xFFFFFFFFu, cq);
        unsigned vm  = __ballot_sync(0xFFFFFFFFu, valid);
        unsigned grp = mm & vm;
        int base = 0;
        if (valid) base = hist[w][cq];          // converged read (bcast per group)
        __syncwarp();                            // reads before cursor update
        if (valid) {
            int rank = __popc(grp & ((1u << lane) - 1));
            int slot = base + rank;
            if (slot < BKT_CAP) {
                float term = __fmul_rn(__fmul_rn(disl[rl], disl[cl]), xwgl[rl]);
                g_bktf[(size_t)(g * NODES_PER_GRAPH + cl) * BKT_CAP + slot] = term;
            }
            if (lane == __ffs(grp) - 1)          // group leader advances cursor
                hist[w][cq] = base + __popc(grp);
        }
        __syncwarp();                            // cursor visible next iteration
    }
}

// One WARP per destination node: terms are already in ascending-edge-id order;
// sequential fp32 left-fold via register shuffles (bit-replicates XLA:CPU's
// serial scatter-add). Predicated adds — no spurious +0.0 terms.
__global__ __launch_bounds__(256) void k_fold() {
    int w    = threadIdx.x >> 5;
    int lane = threadIdx.x & 31;
    int c    = blockIdx.x * 8 + w;
    int n    = g_degi[c];
    if (n > BKT_CAP) n = BKT_CAP;
    const float* b = &g_bktf[(size_t)c * BKT_CAP];
    float v0 = (lane < n)      ? b[lane]      : 0.0f;
    float v1 = (32 + lane < n) ? b[32 + lane] : 0.0f;
    float s = 0.0f;
#pragma unroll
    for (int j = 0; j < 32; j++) {
        float u = __shfl_sync(0xFFFFFFFFu, v0, j);
        if (j < n) s = __fadd_rn(s, u);
    }
#pragma unroll
    for (int j = 0; j < 32; j++) {
        float u = __shfl_sync(0xFFFFFFFFu, v1, j);
        if (32 + j < n) s = __fadd_rn(s, u);
    }
    for (int i = 64; i < n; i++)               // rare tail (deg > 64)
        s = __fadd_rn(s, b[i]);
    if (lane == 0) g_gcn[c] = s;
}

// per-graph full bitonic sort of 1024 (score, idx) keys.
// key = (~ordered(score) << 32) | idx -> ascending sort == descending score,
// ties broken by lower original index (matches jax.lax.top_k).
// Also writes batch_new (fused).
__global__ __launch_bounds__(512) void k_sort(const float* __restrict__ b1,
                                              const float* __restrict__ bg,
                                              float* __restrict__ out) {
    __shared__ unsigned long long keys[NODES_PER_GRAPH];
    __shared__ float sc[NODES_PER_GRAPH];
    int g = blockIdx.x;
    float b1v = b1[0], bgv = bg[0];

    for (int i = threadIdx.x; i < NODES_PER_GRAPH; i += 512) {
        int n = g * NODES_PER_GRAPH + i;
        // 0.5* mults exact (pow2); single rounding in final add, like ref
        float s = __fadd_rn(__fmul_rn(0.5f, __fadd_rn(g_xw1[n], b1v)),
                            __fmul_rn(0.5f, __fadd_rn(g_gcn[n], bgv)));
        sc[i] = s;
        unsigned u = __float_as_uint(s);
        u ^= (u & 0x80000000u) ? 0xFFFFFFFFu : 0x80000000u;  // monotonic asc map
        u = ~u;                                              // descending score
        keys[i] = ((unsigned long long)u << 32) | (unsigned)i;
    }
    __syncthreads();

    for (int k = 2; k <= NODES_PER_GRAPH; k <<= 1) {
        for (int j = k >> 1; j > 0; j >>= 1) {
            int t = threadIdx.x;
            int i = 2 * t - (t & (j - 1));   // index with bit j clear
            int ixj = i | j;
            unsigned long long a = keys[i], bb = keys[ixj];
            bool asc = ((i & k) == 0);
            if ((a > bb) == asc) { keys[i] = bb; keys[ixj] = a; }
            __syncthreads();
        }
    }

    for (int j = threadIdx.x; j < NODES_PER_GRAPH; j += 512) {
        int li = (int)(keys[j] & 0xFFFFFFFFull);
        int n  = g * NODES_PER_GRAPH + li;
        if (j < KSEL) {
            int pos = g * KSEL + j;
            g_perm[pos]      = n;
            g_mult[pos]      = tanhf(sc[li]);
            g_nodemap[n]     = pos;
            out[OUT_B + pos] = (float)g;   // fused batch_new
        } else {
            g_nodemap[n]     = -1;
        }
    }
}

// Fused epilogue: blocks [0, GATHER_BLOCKS) gather x_new; the rest relabel edges.
__global__ void k_epilogue(const float4* __restrict__ x4,
                           const int4* __restrict__ ei4,
                           float* __restrict__ out) {
    int b = blockIdx.x;
    if (b < GATHER_BLOCKS) {
        // x_new[i] = x[perm[i]] * tanh(score[perm[i]])   (float4 lanes)
        int tid = b * 256 + threadIdx.x;
        int i = tid >> 6;         // kept-row index
        int q = tid & 63;         // float4 lane within row
        float m = g_mult[i];
        float4 v = x4[(size_t)g_perm[i] * D_VEC4 + q];
        v.x = __fmul_rn(v.x, m); v.y = __fmul_rn(v.y, m);
        v.z = __fmul_rn(v.z, m); v.w = __fmul_rn(v.w, m);
        ((float4*)out)[tid] = v;
    } else {
        // relabel edges, 4 edges/thread; invalid edges -> (-1,-1)
        int t = (b - GATHER_BLOCKS) * 256 + threadIdx.x;
        if (t >= N_EDGES / 4) return;
        int4 r = ei4[t];
        int4 c = ei4[N_EDGES / 4 + t];
        int er0 = g_nodemap[r.x], ec0 = g_nodemap[c.x];
        int er1 = g_nodemap[r.y], ec1 = g_nodemap[c.y];
        int er2 = g_nodemap[r.z], ec2 = g_nodemap[c.z];
        int er3 = g_nodemap[r.w], ec3 = g_nodemap[c.w];
        float4 ro, co;
        ro.x = (er0 >= 0 && ec0 >= 0) ? (float)er0 : -1.0f;
        co.x = (er0 >= 0 && ec0 >= 0) ? (float)ec0 : -1.0f;
        ro.y = (er1 >= 0 && ec1 >= 0) ? (float)er1 : -1.0f;
        co.y = (er1 >= 0 && ec1 >= 0) ? (float)ec1 : -1.0f;
        ro.z = (er2 >= 0 && ec2 >= 0) ? (float)er2 : -1.0f;
        co.z = (er2 >= 0 && ec2 >= 0) ? (float)ec2 : -1.0f;
        ro.w = (er3 >= 0 && ec3 >= 0) ? (float)er3 : -1.0f;
        co.w = (er3 >= 0 && ec3 >= 0) ? (float)ec3 : -1.0f;
        ((float4*)(out + OUT_E))[t]           = ro;
        ((float4*)(out + OUT_E + N_EDGES))[t] = co;
    }
}

// ---------------- launch ----------------
extern "C" void kernel_launch(void* const* d_in, const int* in_sizes, int n_in,
                              void* d_out, int out_size) {
    const float* x   = (const float*)d_in[0];
    const int*   ei  = (const int*)  d_in[1];
    // d_in[2] = batch (unused: analytic)
    const float* w1  = (const float*)d_in[3];
    const float* b1  = (const float*)d_in[4];
    const float* wg  = (const float*)d_in[5];
    const float* bg  = (const float*)d_in[6];
    float* out = (float*)d_out;

    k_dot<<<N_NODES / 128, 128>>>((const float4*)x, w1, wg);
    k_degdis<<<N_GRAPHS, 512>>>((const int4*)ei);
    k_scatter4<<<N_GRAPHS * NQ, 512>>>(ei, ei + N_EDGES);
    k_fold<<<N_NODES / 8, 256>>>();
    k_sort<<<N_GRAPHS, 512>>>(b1, bg, out);
    k_epilogue<<<EPI_BLOCKS, 256>>>((const float4*)x, (const int4*)ei, out);
}

// round 16
// speedup vs baseline: 1.1623x; 1.0719x over previous
#include <cuda_runtime.h>
#include <cuda_bf16.h>
#include <stdint.h>

// ---------------- problem constants ----------------
#define N_GRAPHS        64
#define NODES_PER_GRAPH 1024
#define N_NODES         (N_GRAPHS * NODES_PER_GRAPH)   // 65536
#define N_EDGES         (N_NODES * 32)                 // 2097152
#define EPG             (N_EDGES / N_GRAPHS)           // 32768 edges per graph
#define D_FEAT          256
#define D_VEC4          (D_FEAT / 4)                   // 64
#define KSEL            512                            // kept nodes per graph
#define N_KEPT          (N_GRAPHS * KSEL)              // 32768
#define BKT_CAP         96                             // max in-degree (Binom mean 32, sd 5.6)

// k_scatter4 geometry: 4 destination-quarters per graph, 16 warps per block
#define NQ              4
#define C_PER_Q         (NODES_PER_GRAPH / NQ)         // 256
#define SC_WARPS        16
#define CHUNK_EDGES     (EPG / SC_WARPS)               // 2048
#define CH_ITERS        (CHUNK_EDGES / 32)             // 64

// output layout (flattened, float32): x_new | new_edge_index | batch_new
#define OUT_E  (N_KEPT * D_FEAT)                       // 8388608
#define OUT_B  (OUT_E + 2 * N_EDGES)                   // 12582912

// fused epilogue grid split
#define GATHER_BLOCKS  ((N_KEPT * D_VEC4) / 256)       // 8192
#define EDGE_BLOCKS    ((N_EDGES / 4) / 256)           // 2048
#define EPI_BLOCKS     (GATHER_BLOCKS + EDGE_BLOCKS)   // 10240

// ---------------- device scratch (no allocation allowed) ----------------
__device__ float g_xw1[N_NODES];
__device__ float g_xwg[N_NODES];
__device__ float g_dis[N_NODES];
__device__ int   g_degi[N_NODES];
__device__ float g_gcn[N_NODES];
// TRANSPOSED buckets: plane per slot, node-contiguous -> coalesced fold loads.
// +8 slack planes so the fold's 8-wide predicated tail stays in-bounds.
__device__ float g_bktfT[(size_t)(BKT_CAP + 8) * N_NODES];
__device__ int   g_perm[N_KEPT];
__device__ float g_mult[N_KEPT];
__device__ int   g_nodemap[N_NODES];

// ---------------- kernels ----------------

// no-op spacer: positions k_scatter4 at launch #4 so ncu (-s 5 -c 1,
// observed to capture ~the 4th launch) profiles it next round.
__global__ void k_nop() {}

// One THREAD per node row; strict sequential FMA chain over k ascending —
// replicates XLA:CPU gemv per-output accumulation order.
__global__ __launch_bounds__(128) void k_dot(const float4* __restrict__ x4,
                                             const float* __restrict__ w1,
                                             const float* __restrict__ wg) {
    __shared__ float s_w1[D_FEAT];
    __shared__ float s_wg[D_FEAT];
    int tid = threadIdx.x;
    for (int i = tid; i < D_FEAT; i += 128) {
        s_w1[i] = w1[i];
        s_wg[i] = wg[i];
    }
    __syncthreads();
    int row = blockIdx.x * 128 + tid;
    const float4* xr = x4 + (size_t)row * D_VEC4;
    float s1 = 0.f, s2 = 0.f;
#pragma unroll 8
    for (int q = 0; q < D_VEC4; q++) {
        float4 xv = xr[q];
        int k = q * 4;
        s1 = __fmaf_rn(xv.x, s_w1[k + 0], s1);
        s1 = __fmaf_rn(xv.y, s_w1[k + 1], s1);
        s1 = __fmaf_rn(xv.z, s_w1[k + 2], s1);
        s1 = __fmaf_rn(xv.w, s_w1[k + 3], s1);
        s2 = __fmaf_rn(xv.x, s_wg[k + 0], s2);
        s2 = __fmaf_rn(xv.y, s_wg[k + 1], s2);
        s2 = __fmaf_rn(xv.z, s_wg[k + 2], s2);
        s2 = __fmaf_rn(xv.w, s_wg[k + 3], s2);
    }
    g_xw1[row] = s1;
    g_xwg[row] = s2;
}

// One block per graph: smem degree histogram, fused dis = 1/sqrt(deg).
// (R8-proven; integer smem atomics — order-independent, exact.)
__global__ __launch_bounds__(512) void k_degdis(const int4* __restrict__ ei4) {
    __shared__ int h[NODES_PER_GRAPH];
    int g = blockIdx.x;
    int tid = threadIdx.x;
    for (int i = tid; i < NODES_PER_GRAPH; i += 512) h[i] = 0;
    __syncthreads();
    int base4 = g * (EPG / 4);
    for (int t = tid; t < EPG / 4; t += 512) {
        int4 r = ei4[base4 + t];
        int4 c = ei4[N_EDGES / 4 + base4 + t];
        if (r.x != c.x) atomicAdd(&h[c.x & (NODES_PER_GRAPH - 1)], 1);
        if (r.y != c.y) atomicAdd(&h[c.y & (NODES_PER_GRAPH - 1)], 1);
        if (r.z != c.z) atomicAdd(&h[c.z & (NODES_PER_GRAPH - 1)], 1);
        if (r.w != c.w) atomicAdd(&h[c.w & (NODES_PER_GRAPH - 1)], 1);
    }
    __syncthreads();
    for (int i = tid; i < NODES_PER_GRAPH; i += 512) {
        int d = h[i];
        // 1.0f/sqrtf, both correctly rounded (matches XLA CPU rsqrt)
        g_dis[g * NODES_PER_GRAPH + i] =
            (d > 0) ? __fdiv_rn(1.0f, __fsqrt_rn((float)d)) : 0.0f;
    }
}

// 4 blocks per graph (one per destination-QUARTER): deterministic ORDERED
// scatter into the TRANSPOSED bucket array. Block-private cursors, no global
// prefix. Chunk order (warp asc) x intra-chunk edge order = ascending edge id.
// term = fl(fl(dis_r*dis_c) * xwg_r) — exactly the reference expression tree.
__global__ __launch_bounds__(512) void k_scatter4(const int* __restrict__ row,
                                                  const int* __restrict__ col) {
    __shared__ int   hist[SC_WARPS][C_PER_Q];            // 16 KB
    __shared__ float disl[NODES_PER_GRAPH];              // 4 KB
    __shared__ float xwgl[NODES_PER_GRAPH];              // 4 KB
    int g    = blockIdx.x >> 2;
    int h    = blockIdx.x & 3;                           // quarter
    int tid  = threadIdx.x;
    int w    = tid >> 5;
    int lane = tid & 31;

    for (int i = tid; i < NODES_PER_GRAPH; i += 512) {
        disl[i] = g_dis[g * NODES_PER_GRAPH + i];
        xwgl[i] = g_xwg[g * NODES_PER_GRAPH + i];
    }
    for (int i = tid; i < SC_WARPS * C_PER_Q; i += 512)
        ((int*)hist)[i] = 0;
    __syncthreads();

    int ebase = g * EPG + w * CHUNK_EDGES;

    // phase 1: per-warp-chunk histogram of own-quarter dsts
#pragma unroll 2
    for (int it = 0; it < CH_ITERS; it++) {
        int e = ebase + it * 32 + lane;
        int rv = row[e], cv = col[e];
        int cl = cv & (NODES_PER_GRAPH - 1);
        if (rv != cv && (cl >> 8) == h)
            atomicAdd(&hist[w][cl & (C_PER_Q - 1)], 1);
    }
    __syncthreads();

    // phase 2: exclusive prefix over chunks per dst; write g_degi
    if (tid < C_PER_Q) {
        int run = 0;
#pragma unroll
        for (int ww = 0; ww < SC_WARPS; ww++) {
            int t = hist[ww][tid];
            hist[ww][tid] = run;
            run += t;
        }
        g_degi[g * NODES_PER_GRAPH + h * C_PER_Q + tid] = run;
    }
    __syncthreads();

    // phase 3: ordered scatter (warp walks its chunk in ascending edge id)
    for (int it = 0; it < CH_ITERS; it++) {
        int e  = ebase + it * 32 + lane;
        int rv = row[e], cv = col[e];
        int rl = rv & (NODES_PER_GRAPH - 1);
        int cl = cv & (NODES_PER_GRAPH - 1);
        int cq = cl & (C_PER_Q - 1);
        bool valid = (rv != cv) && ((cl >> 8) == h);
        unsigned mm  = __match_any_sync(0xFFFFFFFFu, cq);
        unsigned vm  = __ballot_sync(0xFFFFFFFFu, valid);
        unsigned grp = mm & vm;
        int base = 0;
        if (valid) base = hist[w][cq];          // converged read (bcast per group)
        __syncwarp();                            // reads before cursor update
        if (valid) {
            int rank = __popc(grp & ((1u << lane) - 1));
            int slot = base + rank;
            if (slot < BKT_CAP) {
                float term = __fmul_rn(__fmul_rn(disl[rl], disl[cl]), xwgl[rl]);
                g_bktfT[(size_t)slot * N_NODES + g * NODES_PER_GRAPH + cl] = term;
            }
            if (lane == __ffs(grp) - 1)          // group leader advances cursor
                hist[w][cq] = base + __popc(grp);
        }
        __syncwarp();                            // cursor visible next iteration
    }
}

// One THREAD per destination node (transposed layout -> coalesced loads):
// sequential fp32 left-fold in ascending slot = ascending edge id order —
// bit-replicates XLA:CPU's serial scatter-add. 8-wide load batching for MLP.
__global__ __launch_bounds__(256) void k_fold() {
    int c = blockIdx.x * 256 + threadIdx.x;
    int n = g_degi[c];
    if (n > BKT_CAP) n = BKT_CAP;
    float s = 0.0f;
    for (int base = 0; base < n; base += 8) {
        float buf[8];
#pragma unroll
        for (int j = 0; j < 8; j++) {
            buf[j] = 0.0f;
            if (base + j < n)
                buf[j] = g_bktfT[(size_t)(base + j) * N_NODES + c];
        }
#pragma unroll
        for (int j = 0; j < 8; j++)
            if (base + j < n) s = __fadd_rn(s, buf[j]);
    }
    g_gcn[c] = s;
}

// per-graph full bitonic sort of 1024 (score, idx) keys.
// key = (~ordered(score) << 32) | idx -> ascending sort == descending score,
// ties broken by lower original index (matches jax.lax.top_k).
// Also writes batch_new (fused).
__global__ __launch_bounds__(512) void k_sort(const float* __restrict__ b1,
                                              const float* __restrict__ bg,
                                              float* __restrict__ out) {
    __shared__ unsigned long long keys[NODES_PER_GRAPH];
    __shared__ float sc[NODES_PER_GRAPH];
    int g = blockIdx.x;
    float b1v = b1[0], bgv = bg[0];

    for (int i = threadIdx.x; i < NODES_PER_GRAPH; i += 512) {
        int n = g * NODES_PER_GRAPH + i;
        // 0.5* mults exact (pow2); single rounding in final add, like ref
        float s = __fadd_rn(__fmul_rn(0.5f, __fadd_rn(g_xw1[n], b1v)),
                            __fmul_rn(0.5f, __fadd_rn(g_gcn[n], bgv)));
        sc[i] = s;
        unsigned u = __float_as_uint(s);
        u ^= (u & 0x80000000u) ? 0xFFFFFFFFu : 0x80000000u;  // monotonic asc map
        u = ~u;                                              // descending score
        keys[i] = ((unsigned long long)u << 32) | (unsigned)i;
    }
    __syncthreads();

    for (int k = 2; k <= NODES_PER_GRAPH; k <<= 1) {
        for (int j = k >> 1; j > 0; j >>= 1) {
            int t = threadIdx.x;
            int i = 2 * t - (t & (j - 1));   // index with bit j clear
            int ixj = i | j;
            unsigned long long a = keys[i], bb = keys[ixj];
            bool asc = ((i & k) == 0);
            if ((a > bb) == asc) { keys[i] = bb; keys[ixj] = a; }
            __syncthreads();
        }
    }

    for (int j = threadIdx.x; j < NODES_PER_GRAPH; j += 512) {
        int li = (int)(keys[j] & 0xFFFFFFFFull);
        int n  = g * NODES_PER_GRAPH + li;
        if (j < KSEL) {
            int pos = g * KSEL + j;
            g_perm[pos]      = n;
            g_mult[pos]      = tanhf(sc[li]);
            g_nodemap[n]     = pos;
            out[OUT_B + pos] = (float)g;   // fused batch_new
        } else {
            g_nodemap[n]     = -1;
        }
    }
}

// Fused epilogue: blocks [0, GATHER_BLOCKS) gather x_new; the rest relabel edges.
__global__ void k_epilogue(const float4* __restrict__ x4,
                           const int4* __restrict__ ei4,
                           float* __restrict__ out) {
    int b = blockIdx.x;
    if (b < GATHER_BLOCKS) {
        // x_new[i] = x[perm[i]] * tanh(score[perm[i]])   (float4 lanes)
        int tid = b * 256 + threadIdx.x;
        int i = tid >> 6;         // kept-row index
        int q = tid & 63;         // float4 lane within row
        float m = g_mult[i];
        float4 v = x4[(size_t)g_perm[i] * D_VEC4 + q];
        v.x = __fmul_rn(v.x, m); v.y = __fmul_rn(v.y, m);
        v.z = __fmul_rn(v.z, m); v.w = __fmul_rn(v.w, m);
        ((float4*)out)[tid] = v;
    } else {
        // relabel edges, 4 edges/thread; invalid edges -> (-1,-1)
        int t = (b - GATHER_BLOCKS) * 256 + threadIdx.x;
        if (t >= N_EDGES / 4) return;
        int4 r = ei4[t];
        int4 c = ei4[N_EDGES / 4 + t];
        int er0 = g_nodemap[r.x], ec0 = g_nodemap[c.x];
        int er1 = g_nodemap[r.y], ec1 = g_nodemap[c.y];
        int er2 = g_nodemap[r.z], ec2 = g_nodemap[c.z];
        int er3 = g_nodemap[r.w], ec3 = g_nodemap[c.w];
        float4 ro, co;
        ro.x = (er0 >= 0 && ec0 >= 0) ? (float)er0 : -1.0f;
        co.x = (er0 >= 0 && ec0 >= 0) ? (float)ec0 : -1.0f;
        ro.y = (er1 >= 0 && ec1 >= 0) ? (float)er1 : -1.0f;
        co.y = (er1 >= 0 && ec1 >= 0) ? (float)ec1 : -1.0f;
        ro.z = (er2 >= 0 && ec2 >= 0) ? (float)er2 : -1.0f;
        co.z = (er2 >= 0 && ec2 >= 0) ? (float)ec2 : -1.0f;
        ro.w = (er3 >= 0 && ec3 >= 0) ? (float)er3 : -1.0f;
        co.w = (er3 >= 0 && ec3 >= 0) ? (float)ec3 : -1.0f;
        ((float4*)(out + OUT_E))[t]           = ro;
        ((float4*)(out + OUT_E + N_EDGES))[t] = co;
    }
}

// ---------------- launch ----------------
extern "C" void kernel_launch(void* const* d_in, const int* in_sizes, int n_in,
                              void* d_out, int out_size) {
    const float* x   = (const float*)d_in[0];
    const int*   ei  = (const int*)  d_in[1];
    // d_in[2] = batch (unused: analytic)
    const float* w1  = (const float*)d_in[3];
    const float* b1  = (const float*)d_in[4];
    const float* wg  = (const float*)d_in[5];
    const float* bg  = (const float*)d_in[6];
    float* out = (float*)d_out;

    k_dot<<<N_NODES / 128, 128>>>((const float4*)x, w1, wg);        // #1
    k_degdis<<<N_GRAPHS, 512>>>((const int4*)ei);                   // #2
    k_nop<<<1, 32>>>();                                             // #3 (spacer)
    k_scatter4<<<N_GRAPHS * NQ, 512>>>(ei, ei + N_EDGES);           // #4 <- profiled
    k_fold<<<N_NODES / 256, 256>>>();                               // #5
    k_sort<<<N_GRAPHS, 512>>>(b1, bg, out);                         // #6
    k_epilogue<<<EPI_BLOCKS, 256>>>((const float4*)x, (const int4*)ei, out); // #7
}